// round 4
// baseline (speedup 1.0000x reference)
#include <cuda_runtime.h>

#define BATCH 64
#define TT 512
#define II 512
#define HH 512

typedef unsigned long long ull;

// ---- packed f32x2 helpers (sm_100+) ----
__device__ __forceinline__ ull pack2(float x, float y) {
    ull r; asm("mov.b64 %0, {%1, %2};" : "=l"(r) : "f"(x), "f"(y)); return r;
}
__device__ __forceinline__ void unpack2(ull v, float& x, float& y) {
    asm("mov.b64 {%0, %1}, %2;" : "=f"(x), "=f"(y) : "l"(v));
}
__device__ __forceinline__ ull ffma2(ull a, ull b, ull c) {
    ull d; asm("fma.rn.f32x2 %0, %1, %2, %3;" : "=l"(d) : "l"(a), "l"(b), "l"(c)); return d;
}
__device__ __forceinline__ ull fadd2(ull a, ull b) {
    ull d; asm("add.rn.f32x2 %0, %1, %2;" : "=l"(d) : "l"(a), "l"(b)); return d;
}

// ---- persistent device state (allocation-free); ping-pong h buffers ----
__device__ float g_h[2][BATCH][HH];

// ---------------------------------------------------------------------------
// Phase 1: xw = X @ Wx + bx + bh  (M=32768, N=512, K=512) -> mem region of out.
// 128x128x8 tile, double-buffered smem, f32x2 FFMA.  (R2 version — fastest.)
// ---------------------------------------------------------------------------
__global__ __launch_bounds__(256, 2) void gemm_xw_kernel(
    const float* __restrict__ X, const float* __restrict__ Wx,
    const float* __restrict__ bx, const float* __restrict__ bh,
    float* __restrict__ out)
{
    __shared__ float As[2][8][128];
    __shared__ float Bs[2][8][128];

    const int tid = threadIdx.x;
    const int bm = blockIdx.y * 128;
    const int bn = blockIdx.x * 128;
    const int ty = tid >> 4;
    const int tx = tid & 15;

    const int arow = tid >> 1;
    const int akc  = (tid & 1) * 4;
    const int brow = tid >> 5;
    const int bcc  = (tid & 31) * 4;

    const float* Ag = X + (size_t)(bm + arow) * II + akc;
    const float* Bg = Wx + (size_t)brow * HH + bn + bcc;

    {
        float4 av = *(const float4*)Ag;
        float4 bv = *(const float4*)Bg;
        As[0][akc+0][arow] = av.x;
        As[0][akc+1][arow] = av.y;
        As[0][akc+2][arow] = av.z;
        As[0][akc+3][arow] = av.w;
        *(float4*)&Bs[0][brow][bcc] = bv;
    }
    __syncthreads();

    ull acc[8][4];
#pragma unroll
    for (int i = 0; i < 8; i++)
#pragma unroll
        for (int j = 0; j < 4; j++) acc[i][j] = 0ull;

    const int NT = II / 8;
    for (int kt = 0; kt < NT; kt++) {
        const int cur = kt & 1;
        float4 av, bv;
        if (kt + 1 < NT) {
            av = *(const float4*)(Ag + (kt + 1) * 8);
            bv = *(const float4*)(Bg + (size_t)(kt + 1) * 8 * HH);
        }
#pragma unroll
        for (int kk = 0; kk < 8; kk++) {
            float4 a0 = *(const float4*)&As[cur][kk][ty * 8];
            float4 a1 = *(const float4*)&As[cur][kk][ty * 8 + 4];
            float4 b0 = *(const float4*)&Bs[cur][kk][tx * 8];
            float4 b1 = *(const float4*)&Bs[cur][kk][tx * 8 + 4];
            ull bp[4] = { pack2(b0.x,b0.y), pack2(b0.z,b0.w),
                          pack2(b1.x,b1.y), pack2(b1.z,b1.w) };
            float aa[8] = { a0.x,a0.y,a0.z,a0.w, a1.x,a1.y,a1.z,a1.w };
#pragma unroll
            for (int i = 0; i < 8; i++) {
                ull ap = pack2(aa[i], aa[i]);
#pragma unroll
                for (int j = 0; j < 4; j++) acc[i][j] = ffma2(ap, bp[j], acc[i][j]);
            }
        }
        if (kt + 1 < NT) {
            const int nxt = cur ^ 1;
            __syncthreads();
            As[nxt][akc+0][arow] = av.x;
            As[nxt][akc+1][arow] = av.y;
            As[nxt][akc+2][arow] = av.z;
            As[nxt][akc+3][arow] = av.w;
            *(float4*)&Bs[nxt][brow][bcc] = bv;
            __syncthreads();
        }
    }

    const int n0 = bn + tx * 8;
    float bias[8];
#pragma unroll
    for (int j = 0; j < 8; j++) bias[j] = bx[n0 + j] + bh[n0 + j];

#pragma unroll
    for (int i = 0; i < 8; i++) {
        const int m = bm + ty * 8 + i;
        float o[8];
#pragma unroll
        for (int j = 0; j < 4; j++) unpack2(acc[i][j], o[j*2], o[j*2+1]);
        float4 v0 = make_float4(o[0]+bias[0], o[1]+bias[1], o[2]+bias[2], o[3]+bias[3]);
        float4 v1 = make_float4(o[4]+bias[4], o[5]+bias[5], o[6]+bias[6], o[7]+bias[7]);
        *(float4*)&out[(size_t)m * HH + n0]     = v0;
        *(float4*)&out[(size_t)m * HH + n0 + 4] = v1;
    }
}

// ---------------------------------------------------------------------------
// Phase 2: recurrence with CLUSTERS. Grid = 128 CTAs, cluster = 8 CTAs.
// Cluster c handles batches [4c, 4c+4); CTA rank r handles cols [64r, 64r+64).
// Batches are independent, so sync is cluster.sync (no grid barrier).
// Wh slab in registers (64 packed j-pairs/thread); h dup'd in 16KB smem.
// ---------------------------------------------------------------------------
__global__ __launch_bounds__(256, 1) __cluster_dims__(8, 1, 1)
void rnn_kernel(const float* __restrict__ Wh,   // [512,512] k-major
                float* __restrict__ out)        // mem [64,512,512] then hid [64,512]
{
    __shared__ ull hd[4][HH];        // dup'd h for 4 cluster batches (16KB)
    __shared__ ull part[8][4][32];   // kt x b x jpair partials (8KB)

    const int tid = threadIdx.x;
    const int kt  = tid >> 5;        // 0..7   k-chunk of 64
    const int jp  = tid & 31;        // jpair within the 64-col slice
    const int r   = blockIdx.x & 7;  // cluster rank -> cols [64r, 64r+64)
    const int c   = blockIdx.x >> 3; // cluster id   -> batches [4c, 4c+4)
    const int j0  = r * 64 + jp * 2;

    // weights: w2[kl] = (Wh[k][j0], Wh[k][j0+1]),  k = kt*64 + kl
    ull w2[64];
#pragma unroll
    for (int kl = 0; kl < 64; kl++) {
        const float* w = &Wh[(size_t)(kt * 64 + kl) * HH + j0];
        w2[kl] = pack2(w[0], w[1]);
    }

    // reducer/store mapping for tid < 128
    const int rb  = tid >> 5;        // 0..3 local batch
    const int rjp = tid & 31;
    const int gb  = c * 4 + rb;
    const int gj  = r * 64 + rjp * 2;

    float* mem = out;
    float* hid = out + (size_t)BATCH * TT * HH;

    for (int t = 0; t < TT; t++) {
        float2 xw;
        if (tid < 128)
            xw = __ldcg((const float2*)&mem[((size_t)gb * TT + t) * HH + gj]);

        ull acc0 = 0ull, acc1 = 0ull, acc2 = 0ull, acc3 = 0ull;
        if (t > 0) {
            const ulonglong2* h0 = (const ulonglong2*)&hd[0][kt * 64];
            const ulonglong2* h1 = (const ulonglong2*)&hd[1][kt * 64];
            const ulonglong2* h2 = (const ulonglong2*)&hd[2][kt * 64];
            const ulonglong2* h3 = (const ulonglong2*)&hd[3][kt * 64];
#pragma unroll
            for (int i = 0; i < 32; i++) {
                ulonglong2 v0 = h0[i], v1 = h1[i], v2 = h2[i], v3 = h3[i];
                ull wa = w2[2 * i], wb = w2[2 * i + 1];
                acc0 = ffma2(v0.x, wa, acc0);
                acc1 = ffma2(v1.x, wa, acc1);
                acc2 = ffma2(v2.x, wa, acc2);
                acc3 = ffma2(v3.x, wa, acc3);
                acc0 = ffma2(v0.y, wb, acc0);
                acc1 = ffma2(v1.y, wb, acc1);
                acc2 = ffma2(v2.y, wb, acc2);
                acc3 = ffma2(v3.y, wb, acc3);
            }
        }
        part[kt][0][jp] = acc0;
        part[kt][1][jp] = acc1;
        part[kt][2][jp] = acc2;
        part[kt][3][jp] = acc3;
        __syncthreads();

        if (tid < 128) {
            ull sA = fadd2(part[0][rb][rjp], part[1][rb][rjp]);
            ull sB = fadd2(part[2][rb][rjp], part[3][rb][rjp]);
            ull sC = fadd2(part[4][rb][rjp], part[5][rb][rjp]);
            ull sD = fadd2(part[6][rb][rjp], part[7][rb][rjp]);
            ull s  = fadd2(fadd2(sA, sB), fadd2(sC, sD));
            float a0, a1; unpack2(s, a0, a1);
            float2 val = make_float2(tanhf(xw.x + a0), tanhf(xw.y + a1));
            *(float2*)&mem[((size_t)gb * TT + t) * HH + gj] = val;
            __stcg((float2*)&g_h[(t + 1) & 1][gb][gj], val);
            if (t == TT - 1)
                *(float2*)&hid[(size_t)gb * HH + gj] = val;
        }

        if (t < TT - 1) {
            // cluster barrier: release our h stores, acquire peers' h stores
            asm volatile("barrier.cluster.arrive.aligned;" ::: "memory");
            asm volatile("barrier.cluster.wait.aligned;"   ::: "memory");

            // stage dup'd h for next step: 4 batches x 512 floats from L2
            const float2* gh = (const float2*)&g_h[(t + 1) & 1][c * 4][0];
            ulonglong2* hdl = (ulonglong2*)&hd[0][0];
#pragma unroll
            for (int i = 0; i < 4; i++) {
                int e = tid + i * 256;            // 0..1023 = 4 batches x 256
                float2 hv = __ldcg(gh + e);
                ulonglong2 dv;
                dv.x = pack2(hv.x, hv.x);
                dv.y = pack2(hv.y, hv.y);
                hdl[e] = dv;
            }
            __syncthreads();
        }
    }
}

// ---------------------------------------------------------------------------
extern "C" void kernel_launch(void* const* d_in, const int* in_sizes, int n_in,
                              void* d_out, int out_size) {
    const float* x  = (const float*)d_in[0];  // [64, 512, 512]
    const float* Wx = (const float*)d_in[1];  // [512, 512]
    const float* Wh = (const float*)d_in[2];  // [512, 512]
    const float* bx = (const float*)d_in[3];  // [1, 512]
    const float* bh = (const float*)d_in[4];  // [1, 512]
    float* out = (float*)d_out;

    dim3 ggrid(HH / 128, (BATCH * TT) / 128);   // (4, 256)
    gemm_xw_kernel<<<ggrid, 256>>>(x, Wx, bx, bh, out);

    rnn_kernel<<<128, 256>>>(Wh, out);
}

// round 5
// speedup vs baseline: 1.0006x; 1.0006x over previous
#include <cuda_runtime.h>

#define BATCH 64
#define TT 512
#define II 512
#define HH 512

typedef unsigned long long ull;

// ---- packed f32x2 helpers (sm_100+) ----
__device__ __forceinline__ ull pack2(float x, float y) {
    ull r; asm("mov.b64 %0, {%1, %2};" : "=l"(r) : "f"(x), "f"(y)); return r;
}
__device__ __forceinline__ void unpack2(ull v, float& x, float& y) {
    asm("mov.b64 {%0, %1}, %2;" : "=f"(x), "=f"(y) : "l"(v));
}
__device__ __forceinline__ ull ffma2(ull a, ull b, ull c) {
    ull d; asm("fma.rn.f32x2 %0, %1, %2, %3;" : "=l"(d) : "l"(a), "l"(b), "l"(c)); return d;
}
__device__ __forceinline__ ull fadd2(ull a, ull b) {
    ull d; asm("add.rn.f32x2 %0, %1, %2;" : "=l"(d) : "l"(a), "l"(b)); return d;
}

// ---- persistent device state (allocation-free); ping-pong h buffers ----
__device__ float g_h[2][BATCH][HH];

// ---------------------------------------------------------------------------
// Phase 1: xw = X @ Wx + bx + bh  (M=32768, N=512, K=512) -> mem region of out.
// 128x128x8 tile, double-buffered smem, f32x2 FFMA.  (R2 version — fastest.)
// ---------------------------------------------------------------------------
__global__ __launch_bounds__(256, 2) void gemm_xw_kernel(
    const float* __restrict__ X, const float* __restrict__ Wx,
    const float* __restrict__ bx, const float* __restrict__ bh,
    float* __restrict__ out)
{
    __shared__ float As[2][8][128];
    __shared__ float Bs[2][8][128];

    const int tid = threadIdx.x;
    const int bm = blockIdx.y * 128;
    const int bn = blockIdx.x * 128;
    const int ty = tid >> 4;
    const int tx = tid & 15;

    const int arow = tid >> 1;
    const int akc  = (tid & 1) * 4;
    const int brow = tid >> 5;
    const int bcc  = (tid & 31) * 4;

    const float* Ag = X + (size_t)(bm + arow) * II + akc;
    const float* Bg = Wx + (size_t)brow * HH + bn + bcc;

    {
        float4 av = *(const float4*)Ag;
        float4 bv = *(const float4*)Bg;
        As[0][akc+0][arow] = av.x;
        As[0][akc+1][arow] = av.y;
        As[0][akc+2][arow] = av.z;
        As[0][akc+3][arow] = av.w;
        *(float4*)&Bs[0][brow][bcc] = bv;
    }
    __syncthreads();

    ull acc[8][4];
#pragma unroll
    for (int i = 0; i < 8; i++)
#pragma unroll
        for (int j = 0; j < 4; j++) acc[i][j] = 0ull;

    const int NT = II / 8;
    for (int kt = 0; kt < NT; kt++) {
        const int cur = kt & 1;
        float4 av, bv;
        if (kt + 1 < NT) {
            av = *(const float4*)(Ag + (kt + 1) * 8);
            bv = *(const float4*)(Bg + (size_t)(kt + 1) * 8 * HH);
        }
#pragma unroll
        for (int kk = 0; kk < 8; kk++) {
            float4 a0 = *(const float4*)&As[cur][kk][ty * 8];
            float4 a1 = *(const float4*)&As[cur][kk][ty * 8 + 4];
            float4 b0 = *(const float4*)&Bs[cur][kk][tx * 8];
            float4 b1 = *(const float4*)&Bs[cur][kk][tx * 8 + 4];
            ull bp[4] = { pack2(b0.x,b0.y), pack2(b0.z,b0.w),
                          pack2(b1.x,b1.y), pack2(b1.z,b1.w) };
            float aa[8] = { a0.x,a0.y,a0.z,a0.w, a1.x,a1.y,a1.z,a1.w };
#pragma unroll
            for (int i = 0; i < 8; i++) {
                ull ap = pack2(aa[i], aa[i]);
#pragma unroll
                for (int j = 0; j < 4; j++) acc[i][j] = ffma2(ap, bp[j], acc[i][j]);
            }
        }
        if (kt + 1 < NT) {
            const int nxt = cur ^ 1;
            __syncthreads();
            As[nxt][akc+0][arow] = av.x;
            As[nxt][akc+1][arow] = av.y;
            As[nxt][akc+2][arow] = av.z;
            As[nxt][akc+3][arow] = av.w;
            *(float4*)&Bs[nxt][brow][bcc] = bv;
            __syncthreads();
        }
    }

    const int n0 = bn + tx * 8;
    float bias[8];
#pragma unroll
    for (int j = 0; j < 8; j++) bias[j] = bx[n0 + j] + bh[n0 + j];

#pragma unroll
    for (int i = 0; i < 8; i++) {
        const int m = bm + ty * 8 + i;
        float o[8];
#pragma unroll
        for (int j = 0; j < 4; j++) unpack2(acc[i][j], o[j*2], o[j*2+1]);
        float4 v0 = make_float4(o[0]+bias[0], o[1]+bias[1], o[2]+bias[2], o[3]+bias[3]);
        float4 v1 = make_float4(o[4]+bias[4], o[5]+bias[5], o[6]+bias[6], o[7]+bias[7]);
        *(float4*)&out[(size_t)m * HH + n0]     = v0;
        *(float4*)&out[(size_t)m * HH + n0 + 4] = v1;
    }
}

// ---------------------------------------------------------------------------
// Phase 2: recurrence with CLUSTERS. Grid = 128 CTAs, cluster = 8 CTAs.
// Cluster c handles batches [4c, 4c+4); CTA rank r handles cols [64r, 64r+64).
// Batches are independent, so sync is cluster.sync (no grid barrier).
// Wh slab in registers (64 packed j-pairs/thread); h dup'd in 16KB smem.
// ---------------------------------------------------------------------------
__global__ __launch_bounds__(256, 1) __cluster_dims__(8, 1, 1)
void rnn_kernel(const float* __restrict__ Wh,   // [512,512] k-major
                float* __restrict__ out)        // mem [64,512,512] then hid [64,512]
{
    __shared__ ull hd[4][HH];        // dup'd h for 4 cluster batches (16KB)
    __shared__ ull part[8][4][32];   // kt x b x jpair partials (8KB)

    const int tid = threadIdx.x;
    const int kt  = tid >> 5;        // 0..7   k-chunk of 64
    const int jp  = tid & 31;        // jpair within the 64-col slice
    const int r   = blockIdx.x & 7;  // cluster rank -> cols [64r, 64r+64)
    const int c   = blockIdx.x >> 3; // cluster id   -> batches [4c, 4c+4)
    const int j0  = r * 64 + jp * 2;

    // weights: w2[kl] = (Wh[k][j0], Wh[k][j0+1]),  k = kt*64 + kl
    ull w2[64];
#pragma unroll
    for (int kl = 0; kl < 64; kl++) {
        const float* w = &Wh[(size_t)(kt * 64 + kl) * HH + j0];
        w2[kl] = pack2(w[0], w[1]);
    }

    // reducer/store mapping for tid < 128
    const int rb  = tid >> 5;        // 0..3 local batch
    const int rjp = tid & 31;
    const int gb  = c * 4 + rb;
    const int gj  = r * 64 + rjp * 2;

    float* mem = out;
    float* hid = out + (size_t)BATCH * TT * HH;

    for (int t = 0; t < TT; t++) {
        float2 xw;
        if (tid < 128)
            xw = __ldcg((const float2*)&mem[((size_t)gb * TT + t) * HH + gj]);

        ull acc0 = 0ull, acc1 = 0ull, acc2 = 0ull, acc3 = 0ull;
        if (t > 0) {
            const ulonglong2* h0 = (const ulonglong2*)&hd[0][kt * 64];
            const ulonglong2* h1 = (const ulonglong2*)&hd[1][kt * 64];
            const ulonglong2* h2 = (const ulonglong2*)&hd[2][kt * 64];
            const ulonglong2* h3 = (const ulonglong2*)&hd[3][kt * 64];
#pragma unroll
            for (int i = 0; i < 32; i++) {
                ulonglong2 v0 = h0[i], v1 = h1[i], v2 = h2[i], v3 = h3[i];
                ull wa = w2[2 * i], wb = w2[2 * i + 1];
                acc0 = ffma2(v0.x, wa, acc0);
                acc1 = ffma2(v1.x, wa, acc1);
                acc2 = ffma2(v2.x, wa, acc2);
                acc3 = ffma2(v3.x, wa, acc3);
                acc0 = ffma2(v0.y, wb, acc0);
                acc1 = ffma2(v1.y, wb, acc1);
                acc2 = ffma2(v2.y, wb, acc2);
                acc3 = ffma2(v3.y, wb, acc3);
            }
        }
        part[kt][0][jp] = acc0;
        part[kt][1][jp] = acc1;
        part[kt][2][jp] = acc2;
        part[kt][3][jp] = acc3;
        __syncthreads();

        if (tid < 128) {
            ull sA = fadd2(part[0][rb][rjp], part[1][rb][rjp]);
            ull sB = fadd2(part[2][rb][rjp], part[3][rb][rjp]);
            ull sC = fadd2(part[4][rb][rjp], part[5][rb][rjp]);
            ull sD = fadd2(part[6][rb][rjp], part[7][rb][rjp]);
            ull s  = fadd2(fadd2(sA, sB), fadd2(sC, sD));
            float a0, a1; unpack2(s, a0, a1);
            float2 val = make_float2(tanhf(xw.x + a0), tanhf(xw.y + a1));
            *(float2*)&mem[((size_t)gb * TT + t) * HH + gj] = val;
            __stcg((float2*)&g_h[(t + 1) & 1][gb][gj], val);
            if (t == TT - 1)
                *(float2*)&hid[(size_t)gb * HH + gj] = val;
        }

        if (t < TT - 1) {
            // cluster barrier: release our h stores, acquire peers' h stores
            asm volatile("barrier.cluster.arrive.aligned;" ::: "memory");
            asm volatile("barrier.cluster.wait.aligned;"   ::: "memory");

            // stage dup'd h for next step: 4 batches x 512 floats from L2
            const float2* gh = (const float2*)&g_h[(t + 1) & 1][c * 4][0];
            ulonglong2* hdl = (ulonglong2*)&hd[0][0];
#pragma unroll
            for (int i = 0; i < 4; i++) {
                int e = tid + i * 256;            // 0..1023 = 4 batches x 256
                float2 hv = __ldcg(gh + e);
                ulonglong2 dv;
                dv.x = pack2(hv.x, hv.x);
                dv.y = pack2(hv.y, hv.y);
                hdl[e] = dv;
            }
            __syncthreads();
        }
    }
}

// ---------------------------------------------------------------------------
extern "C" void kernel_launch(void* const* d_in, const int* in_sizes, int n_in,
                              void* d_out, int out_size) {
    const float* x  = (const float*)d_in[0];  // [64, 512, 512]
    const float* Wx = (const float*)d_in[1];  // [512, 512]
    const float* Wh = (const float*)d_in[2];  // [512, 512]
    const float* bx = (const float*)d_in[3];  // [1, 512]
    const float* bh = (const float*)d_in[4];  // [1, 512]
    float* out = (float*)d_out;

    dim3 ggrid(HH / 128, (BATCH * TT) / 128);   // (4, 256)
    gemm_xw_kernel<<<ggrid, 256>>>(x, Wx, bx, bh, out);

    rnn_kernel<<<128, 256>>>(Wh, out);
}

// round 6
// speedup vs baseline: 1.2324x; 1.2317x over previous
#include <cuda_runtime.h>

#define BATCH 64
#define TT 512
#define II 512
#define HH 512

typedef unsigned long long ull;

__device__ __forceinline__ ull pack2(float x, float y) {
    ull r; asm("mov.b64 %0, {%1, %2};" : "=l"(r) : "f"(x), "f"(y)); return r;
}
__device__ __forceinline__ void unpack2(ull v, float& x, float& y) {
    asm("mov.b64 {%0, %1}, %2;" : "=f"(x), "=f"(y) : "l"(v));
}
__device__ __forceinline__ ull ffma2(ull a, ull b, ull c) {
    ull d; asm("fma.rn.f32x2 %0, %1, %2, %3;" : "=l"(d) : "l"(a), "l"(b), "l"(c)); return d;
}
__device__ __forceinline__ ull fadd2(ull a, ull b) {
    ull d; asm("add.rn.f32x2 %0, %1, %2;" : "=l"(d) : "l"(a), "l"(b)); return d;
}
__device__ __forceinline__ unsigned ld_acq(const unsigned* p) {
    unsigned v; asm volatile("ld.acquire.gpu.global.u32 %0, [%1];" : "=r"(v) : "l"(p) : "memory");
    return v;
}
__device__ __forceinline__ void red_rel_add1(unsigned* p) {
    asm volatile("red.release.gpu.global.add.u32 [%0], 1;" :: "l"(p) : "memory");
}

// persistent device state (allocation-free); h in TRANSPOSED layout [j][b]
__device__ float g_hT[2][HH][BATCH];
__device__ unsigned g_bar[4 * 32];   // one counter per batch group, 128B apart

// ---------------------------------------------------------------------------
// Phase 1: xw = X @ Wx + bx + bh  (M=32768,N=512,K=512) -> mem region of out.
// (unchanged R2 version)
// ---------------------------------------------------------------------------
__global__ __launch_bounds__(256, 2) void gemm_xw_kernel(
    const float* __restrict__ X, const float* __restrict__ Wx,
    const float* __restrict__ bx, const float* __restrict__ bh,
    float* __restrict__ out)
{
    __shared__ float As[2][8][128];
    __shared__ float Bs[2][8][128];

    const int tid = threadIdx.x;
    const int bm = blockIdx.y * 128, bn = blockIdx.x * 128;
    const int ty = tid >> 4, tx = tid & 15;
    const int arow = tid >> 1, akc = (tid & 1) * 4;
    const int brow = tid >> 5, bcc = (tid & 31) * 4;

    const float* Ag = X + (size_t)(bm + arow) * II + akc;
    const float* Bg = Wx + (size_t)brow * HH + bn + bcc;

    {
        float4 av = *(const float4*)Ag;
        float4 bv = *(const float4*)Bg;
        As[0][akc+0][arow] = av.x; As[0][akc+1][arow] = av.y;
        As[0][akc+2][arow] = av.z; As[0][akc+3][arow] = av.w;
        *(float4*)&Bs[0][brow][bcc] = bv;
    }
    __syncthreads();

    ull acc[8][4];
#pragma unroll
    for (int i = 0; i < 8; i++)
#pragma unroll
        for (int j = 0; j < 4; j++) acc[i][j] = 0ull;

    const int NT = II / 8;
    for (int kt = 0; kt < NT; kt++) {
        const int cur = kt & 1;
        float4 av, bv;
        if (kt + 1 < NT) {
            av = *(const float4*)(Ag + (kt + 1) * 8);
            bv = *(const float4*)(Bg + (size_t)(kt + 1) * 8 * HH);
        }
#pragma unroll
        for (int kk = 0; kk < 8; kk++) {
            float4 a0 = *(const float4*)&As[cur][kk][ty * 8];
            float4 a1 = *(const float4*)&As[cur][kk][ty * 8 + 4];
            float4 b0 = *(const float4*)&Bs[cur][kk][tx * 8];
            float4 b1 = *(const float4*)&Bs[cur][kk][tx * 8 + 4];
            ull bp[4] = { pack2(b0.x,b0.y), pack2(b0.z,b0.w),
                          pack2(b1.x,b1.y), pack2(b1.z,b1.w) };
            float aa[8] = { a0.x,a0.y,a0.z,a0.w, a1.x,a1.y,a1.z,a1.w };
#pragma unroll
            for (int i = 0; i < 8; i++) {
                ull ap = pack2(aa[i], aa[i]);
#pragma unroll
                for (int j = 0; j < 4; j++) acc[i][j] = ffma2(ap, bp[j], acc[i][j]);
            }
        }
        if (kt + 1 < NT) {
            const int nxt = cur ^ 1;
            __syncthreads();
            As[nxt][akc+0][arow] = av.x; As[nxt][akc+1][arow] = av.y;
            As[nxt][akc+2][arow] = av.z; As[nxt][akc+3][arow] = av.w;
            *(float4*)&Bs[nxt][brow][bcc] = bv;
            __syncthreads();
        }
    }

    const int n0 = bn + tx * 8;
    float bias[8];
#pragma unroll
    for (int j = 0; j < 8; j++) bias[j] = bx[n0 + j] + bh[n0 + j];
#pragma unroll
    for (int i = 0; i < 8; i++) {
        const int m = bm + ty * 8 + i;
        float o[8];
#pragma unroll
        for (int j = 0; j < 4; j++) unpack2(acc[i][j], o[j*2], o[j*2+1]);
        float4 v0 = make_float4(o[0]+bias[0], o[1]+bias[1], o[2]+bias[2], o[3]+bias[3]);
        float4 v1 = make_float4(o[4]+bias[4], o[5]+bias[5], o[6]+bias[6], o[7]+bias[7]);
        *(float4*)&out[(size_t)m * HH + n0]     = v0;
        *(float4*)&out[(size_t)m * HH + n0 + 4] = v1;
    }
}

// ---------------------------------------------------------------------------
// Phase 2: recurrence. 128 CTAs x 256 threads. CTA (bg 0..3, jg 0..31):
// 16 batches x 16 cols. Barrier = per-bg counter (32 arrivals).
// Thread: jq = tid&15 (1 col), kg = tid>>4 (32-k chunk), all 16 batches.
// h staged transposed in smem: h_Ts[k][16b], stride 20 floats.
// Inner loop: 4 LDS.128 -> 8 batch-pair ulls -> 8 FFMA2 (zero packs).
// Reduce: shfl-16 fold + smem partials over 8 warps.
// ---------------------------------------------------------------------------
extern __shared__ char rsm[];

__global__ __launch_bounds__(256, 1) void rnn_kernel(
    const float* __restrict__ Wh,   // [512,512] k-major
    float* __restrict__ out)
{
    float* h_Ts = (float*)rsm;                       // 512 x 20 floats (40KB)
    ull*   part = (ull*)(rsm + 512 * 20 * 4);        // [8][16][10] ull (10KB)

    const int tid = threadIdx.x;
    const int jq  = tid & 15;
    const int kg  = tid >> 4;          // 0..15
    const int w   = tid >> 5;          // warp 0..7
    const int h4  = (tid >> 4) & 1;    // kg LSB (lane bit 4)
    const int jg  = blockIdx.x & 31;
    const int bg  = blockIdx.x >> 5;
    const int jbase = jg * 16, bbase = bg * 16;
    const int j = jbase + jq;

    // weights dup-packed once: w2[i] = (Wh[kg*32+i][j], same)
    ull w2[32];
#pragma unroll
    for (int i = 0; i < 32; i++) {
        float v = Wh[(size_t)(kg * 32 + i) * HH + j];
        w2[i] = pack2(v, v);
    }

    // writer mapping (tid < 128): one (col, batch-pair) each
    const int wjq = tid & 15, wbp = tid >> 4;        // wbp 0..7
    const int wj = jbase + wjq;
    const int wb0 = bbase + wbp * 2;

    float* mem = out;
    float* hid = out + (size_t)BATCH * TT * HH;
    unsigned* bar = &g_bar[bg * 32];

    for (int t = 0; t < TT; t++) {
        float xw0 = 0.f, xw1 = 0.f;
        if (tid < 128) {
            xw0 = __ldg(&mem[((size_t)wb0 * TT + t) * HH + wj]);
            xw1 = __ldg(&mem[((size_t)(wb0 + 1) * TT + t) * HH + wj]);
        }

        ull acc[8];
#pragma unroll
        for (int p = 0; p < 8; p++) acc[p] = 0ull;

        if (t > 0) {
            // wait for all 32 group CTAs to finish step t-1 (acquire)
            if (tid == 0) {
                const unsigned target = (unsigned)t * 32u;
                while (ld_acq(bar) < target) { }
            }
            __syncthreads();

            // stage h_t: g_hT[t&1][j][bbase..+15] -> h_Ts (transposed layout kept)
            const float* gsrc = &g_hT[t & 1][0][0];
#pragma unroll
            for (int i = 0; i < 8; i++) {
                int e = tid + i * 256;          // 0..2047
                int row = e >> 2, q = e & 3;
                float4 v = __ldcg((const float4*)&gsrc[row * BATCH + bbase + q * 4]);
                *(float4*)&h_Ts[row * 20 + q * 4] = v;
            }
            __syncthreads();

            // compute: k = kg*32 + i
            const char* base = (const char*)&h_Ts[kg * 32 * 20];
#pragma unroll
            for (int i = 0; i < 32; i++) {
                const ulonglong2* r = (const ulonglong2*)(base + i * 80);
                ulonglong2 u0 = r[0], u1 = r[1];
                ull wv = w2[i];
                acc[0] = ffma2(u0.x, wv, acc[0]);
                acc[1] = ffma2(u0.y, wv, acc[1]);
                acc[2] = ffma2(u1.x, wv, acc[2]);
                acc[3] = ffma2(u1.y, wv, acc[3]);
                const ulonglong2* r2 = (const ulonglong2*)(base + i * 80 + 32);
                ulonglong2 u2 = r2[0], u3 = r2[1];
                acc[4] = ffma2(u2.x, wv, acc[4]);
                acc[5] = ffma2(u2.y, wv, acc[5]);
                acc[6] = ffma2(u3.x, wv, acc[6]);
                acc[7] = ffma2(u3.y, wv, acc[7]);
            }
        } else {
            __syncthreads();   // keep barrier counts uniform
            __syncthreads();
        }

        // fold across kg LSB (lane bit 4): low lanes keep bp 0..3, high bp 4..7
        ull v[4];
#pragma unroll
        for (int i = 0; i < 4; i++) {
            ull give = h4 ? acc[i] : acc[i + 4];
            ull got  = __shfl_xor_sync(0xFFFFFFFFu, give, 16);
            ull keep = h4 ? acc[i + 4] : acc[i];
            v[i] = fadd2(keep, got);
        }
        // partials: part[w][jq][h4*4 + 0..3]
        {
            ull* dst = &part[(w * 16 + jq) * 10 + h4 * 4];
            ulonglong2 p01; p01.x = v[0]; p01.y = v[1];
            ulonglong2 p23; p23.x = v[2]; p23.y = v[3];
            *(ulonglong2*)&dst[0] = p01;
            *(ulonglong2*)&dst[2] = p23;
        }
        __syncthreads();

        if (tid < 128) {
            ull s = 0ull;
#pragma unroll
            for (int ww = 0; ww < 8; ww++)
                s = fadd2(s, part[(ww * 16 + wjq) * 10 + wbp]);
            float a0, a1; unpack2(s, a0, a1);
            float r0 = tanhf(xw0 + a0);
            float r1 = tanhf(xw1 + a1);
            mem[((size_t)wb0 * TT + t) * HH + wj] = r0;
            mem[((size_t)(wb0 + 1) * TT + t) * HH + wj] = r1;
            float2 hv = make_float2(r0, r1);
            *(float2*)&g_hT[(t + 1) & 1][wj][wb0] = hv;
            if (t == TT - 1) {
                hid[(size_t)wb0 * HH + wj] = r0;
                hid[(size_t)(wb0 + 1) * HH + wj] = r1;
            }
        }

        if (t < TT - 1) {
            __syncthreads();
            if (tid == 0) red_rel_add1(bar);   // release: h stores visible first
        }
    }

    // self-reset the group counter for the next graph replay
    __syncthreads();
    if (tid == 0) {
        red_rel_add1(bar);                      // count -> (TT-1)*32 + 32 total
        if (jg == 0) {
            const unsigned full = (unsigned)TT * 32u;
            while (ld_acq(bar) < full) { }
            atomicExch(bar, 0u);
        }
    }
}

// ---------------------------------------------------------------------------
extern "C" void kernel_launch(void* const* d_in, const int* in_sizes, int n_in,
                              void* d_out, int out_size) {
    const float* x  = (const float*)d_in[0];
    const float* Wx = (const float*)d_in[1];
    const float* Wh = (const float*)d_in[2];
    const float* bx = (const float*)d_in[3];
    const float* bh = (const float*)d_in[4];
    float* out = (float*)d_out;

    const int smem = 512 * 20 * 4 + 8 * 16 * 10 * 8;   // 40960 + 10240
    cudaFuncSetAttribute(rnn_kernel, cudaFuncAttributeMaxDynamicSharedMemorySize, smem);

    dim3 ggrid(HH / 128, (BATCH * TT) / 128);
    gemm_xw_kernel<<<ggrid, 256>>>(x, Wx, bx, bh, out);
    rnn_kernel<<<128, 256, smem>>>(Wh, out);
}

// round 7
// speedup vs baseline: 1.3321x; 1.0809x over previous
#include <cuda_runtime.h>
#include <math.h>

#define BATCH 64
#define TT 512
#define II 512
#define HH 512

typedef unsigned long long ull;

__device__ __forceinline__ ull pack2(float x, float y) {
    ull r; asm("mov.b64 %0, {%1, %2};" : "=l"(r) : "f"(x), "f"(y)); return r;
}
__device__ __forceinline__ void unpack2(ull v, float& x, float& y) {
    asm("mov.b64 {%0, %1}, %2;" : "=f"(x), "=f"(y) : "l"(v));
}
__device__ __forceinline__ ull ffma2(ull a, ull b, ull c) {
    ull d; asm("fma.rn.f32x2 %0, %1, %2, %3;" : "=l"(d) : "l"(a), "l"(b), "l"(c)); return d;
}
__device__ __forceinline__ ull fadd2(ull a, ull b) {
    ull d; asm("add.rn.f32x2 %0, %1, %2;" : "=l"(d) : "l"(a), "l"(b)); return d;
}
__device__ __forceinline__ unsigned ld_acq(const unsigned* p) {
    unsigned v; asm volatile("ld.acquire.gpu.global.u32 %0, [%1];" : "=r"(v) : "l"(p) : "memory");
    return v;
}
__device__ __forceinline__ void red_rel_add1(unsigned* p) {
    asm volatile("red.release.gpu.global.add.u32 [%0], 1;" :: "l"(p) : "memory");
}
__device__ __forceinline__ float tanh_fast(float x) {
    float ax = fabsf(x);
    if (ax < 0.04f) return x * (1.0f - 0.3333333f * x * x);
    float e = __expf(2.0f * x);
    return 1.0f - __fdividef(2.0f, e + 1.0f);
}

// persistent state: h transposed [j][b], ping-pong; per-group counters
__device__ float g_hT[2][HH][BATCH];
__device__ unsigned g_bar[8 * 32];      // 8 groups, 128B apart

// ---------------------------------------------------------------------------
// Phase 1: xw = X @ Wx + bx + bh  (unchanged R2 version)
// ---------------------------------------------------------------------------
__global__ __launch_bounds__(256, 2) void gemm_xw_kernel(
    const float* __restrict__ X, const float* __restrict__ Wx,
    const float* __restrict__ bx, const float* __restrict__ bh,
    float* __restrict__ out)
{
    __shared__ float As[2][8][128];
    __shared__ float Bs[2][8][128];

    const int tid = threadIdx.x;
    const int bm = blockIdx.y * 128, bn = blockIdx.x * 128;
    const int ty = tid >> 4, tx = tid & 15;
    const int arow = tid >> 1, akc = (tid & 1) * 4;
    const int brow = tid >> 5, bcc = (tid & 31) * 4;

    const float* Ag = X + (size_t)(bm + arow) * II + akc;
    const float* Bg = Wx + (size_t)brow * HH + bn + bcc;

    {
        float4 av = *(const float4*)Ag;
        float4 bv = *(const float4*)Bg;
        As[0][akc+0][arow] = av.x; As[0][akc+1][arow] = av.y;
        As[0][akc+2][arow] = av.z; As[0][akc+3][arow] = av.w;
        *(float4*)&Bs[0][brow][bcc] = bv;
    }
    __syncthreads();

    ull acc[8][4];
#pragma unroll
    for (int i = 0; i < 8; i++)
#pragma unroll
        for (int j = 0; j < 4; j++) acc[i][j] = 0ull;

    const int NT = II / 8;
    for (int kt = 0; kt < NT; kt++) {
        const int cur = kt & 1;
        float4 av, bv;
        if (kt + 1 < NT) {
            av = *(const float4*)(Ag + (kt + 1) * 8);
            bv = *(const float4*)(Bg + (size_t)(kt + 1) * 8 * HH);
        }
#pragma unroll
        for (int kk = 0; kk < 8; kk++) {
            float4 a0 = *(const float4*)&As[cur][kk][ty * 8];
            float4 a1 = *(const float4*)&As[cur][kk][ty * 8 + 4];
            float4 b0 = *(const float4*)&Bs[cur][kk][tx * 8];
            float4 b1 = *(const float4*)&Bs[cur][kk][tx * 8 + 4];
            ull bp[4] = { pack2(b0.x,b0.y), pack2(b0.z,b0.w),
                          pack2(b1.x,b1.y), pack2(b1.z,b1.w) };
            float aa[8] = { a0.x,a0.y,a0.z,a0.w, a1.x,a1.y,a1.z,a1.w };
#pragma unroll
            for (int i = 0; i < 8; i++) {
                ull ap = pack2(aa[i], aa[i]);
#pragma unroll
                for (int j = 0; j < 4; j++) acc[i][j] = ffma2(ap, bp[j], acc[i][j]);
            }
        }
        if (kt + 1 < NT) {
            const int nxt = cur ^ 1;
            __syncthreads();
            As[nxt][akc+0][arow] = av.x; As[nxt][akc+1][arow] = av.y;
            As[nxt][akc+2][arow] = av.z; As[nxt][akc+3][arow] = av.w;
            *(float4*)&Bs[nxt][brow][bcc] = bv;
            __syncthreads();
        }
    }

    const int n0 = bn + tx * 8;
    float bias[8];
#pragma unroll
    for (int j = 0; j < 8; j++) bias[j] = bx[n0 + j] + bh[n0 + j];
#pragma unroll
    for (int i = 0; i < 8; i++) {
        const int m = bm + ty * 8 + i;
        float o[8];
#pragma unroll
        for (int j = 0; j < 4; j++) unpack2(acc[i][j], o[j*2], o[j*2+1]);
        float4 v0 = make_float4(o[0]+bias[0], o[1]+bias[1], o[2]+bias[2], o[3]+bias[3]);
        float4 v1 = make_float4(o[4]+bias[4], o[5]+bias[5], o[6]+bias[6], o[7]+bias[7]);
        *(float4*)&out[(size_t)m * HH + n0]     = v0;
        *(float4*)&out[(size_t)m * HH + n0 + 4] = v1;
    }
}

// ---------------------------------------------------------------------------
// Phase 2: recurrence. 128 CTAs x 256 threads.
// CTA (g 0..7, cg 0..15): 8 batches x 32 cols. Barrier group = 16 CTAs,
// counter arrivals = 4 reducer-warp releases per CTA per step.
// Thread: warp w, lane: jq=lane&15 (2 cols), hl=lane>>4, kt=2w+hl (32 k).
// h staged transposed [k][8b] (16KB). Inner: 2 LDS.128 + 8 FFMA2 per k.
// ---------------------------------------------------------------------------
#define PIDX(l, w_, p_) ((l) * 33 + (w_) * 4 + (p_))

__global__ __launch_bounds__(256, 1) void rnn_kernel(
    const float* __restrict__ Wh, float* __restrict__ out)
{
    __shared__ float h_Ts[HH * 8];        // [k][8 batches], 16KB
    __shared__ ull   part[32 * 33];       // padded stride 33, ~8.4KB

    const int tid  = threadIdx.x;
    const int lane = tid & 31;
    const int w    = tid >> 5;
    const int jq   = lane & 15;
    const int hl   = lane >> 4;
    const int kt   = (w << 1) | hl;       // 0..15
    const int cg   = blockIdx.x & 15;
    const int g    = blockIdx.x >> 4;
    const int jbase = cg * 32;
    const int bbase = g * 8;

    // weights: w2[i][c] = dup(Wh[kt*32+i][jbase + jq*2 + c])
    ull w2[32][2];
#pragma unroll
    for (int i = 0; i < 32; i++) {
        float2 wv = *(const float2*)&Wh[(size_t)(kt * 32 + i) * HH + jbase + jq * 2];
        w2[i][0] = pack2(wv.x, wv.x);
        w2[i][1] = pack2(wv.y, wv.y);
    }

    // reducer mapping (tid < 128): col rj, batch pair rp
    const int rjc = tid & 31;
    const int rp  = (tid >> 5) & 3;
    const int rb0 = bbase + rp * 2;
    const int rj  = jbase + rjc;
    const int rlane = ((rjc & 1) << 4) | (rjc >> 1);
    const bool is_red = (tid < 128);

    float* mem = out;
    float* hid = out + (size_t)BATCH * TT * HH;
    unsigned* bar = &g_bar[g * 32];

    for (int t = 0; t < TT; t++) {
        float xw0 = 0.f, xw1 = 0.f;
        if (is_red) {
            xw0 = __ldg(&mem[((size_t)rb0 * TT + t) * HH + rj]);
            xw1 = __ldg(&mem[((size_t)(rb0 + 1) * TT + t) * HH + rj]);
        }

        ull acc[2][4];
#pragma unroll
        for (int p = 0; p < 4; p++) { acc[0][p] = 0ull; acc[1][p] = 0ull; }

        if (t > 0) {
            // per-warp wait: all 16 CTAs x 4 reducer warps released step t-1
            if (lane == 0) {
                const unsigned target = (unsigned)t * 64u;
                while (ld_acq(bar) < target) { }
            }
            __syncwarp();

            // stage h_t: g_hT[t&1][k][bbase..+8) -> h_Ts[k][8]
            const float* gsrc = &g_hT[t & 1][0][0];
#pragma unroll
            for (int i = 0; i < 4; i++) {
                int e = tid + i * 256;            // 0..1023
                int row = e >> 1, q = e & 1;
                float4 v = __ldcg((const float4*)&gsrc[row * BATCH + bbase + q * 4]);
                *(float4*)&h_Ts[row * 8 + q * 4] = v;
            }
            __syncthreads();

            const ulonglong2* hb = (const ulonglong2*)&h_Ts[kt * 32 * 8];
#pragma unroll
            for (int i = 0; i < 32; i++) {
                ulonglong2 u0 = hb[2 * i], u1 = hb[2 * i + 1];
                ull w0 = w2[i][0], w1 = w2[i][1];
                acc[0][0] = ffma2(u0.x, w0, acc[0][0]);
                acc[0][1] = ffma2(u0.y, w0, acc[0][1]);
                acc[0][2] = ffma2(u1.x, w0, acc[0][2]);
                acc[0][3] = ffma2(u1.y, w0, acc[0][3]);
                acc[1][0] = ffma2(u0.x, w1, acc[1][0]);
                acc[1][1] = ffma2(u0.y, w1, acc[1][1]);
                acc[1][2] = ffma2(u1.x, w1, acc[1][2]);
                acc[1][3] = ffma2(u1.y, w1, acc[1][3]);
            }
        }

        // fold across lane bit 4: lane keeps col c = hl, summed over both kt
        ull v[4];
#pragma unroll
        for (int p = 0; p < 4; p++) {
            ull give = hl ? acc[0][p] : acc[1][p];
            ull got  = __shfl_xor_sync(0xFFFFFFFFu, give, 16);
            ull keep = hl ? acc[1][p] : acc[0][p];
            v[p] = fadd2(keep, got);
        }
#pragma unroll
        for (int p = 0; p < 4; p++) part[PIDX(lane, w, p)] = v[p];
        __syncthreads();

        if (is_red) {
            ull s = part[PIDX(rlane, 0, rp)];
#pragma unroll
            for (int ww = 1; ww < 8; ww++) s = fadd2(s, part[PIDX(rlane, ww, rp)]);
            float a0, a1; unpack2(s, a0, a1);
            float r0 = tanh_fast(xw0 + a0);
            float r1 = tanh_fast(xw1 + a1);
            mem[((size_t)rb0 * TT + t) * HH + rj] = r0;
            mem[((size_t)(rb0 + 1) * TT + t) * HH + rj] = r1;
            *(float2*)&g_hT[(t + 1) & 1][rj][rb0] = make_float2(r0, r1);
            if (t == TT - 1) {
                hid[(size_t)rb0 * HH + rj] = r0;
                hid[(size_t)(rb0 + 1) * HH + rj] = r1;
            }
            if (t < TT - 1) {
                __syncwarp();
                if (lane == 0) red_rel_add1(bar);   // ordered after warp's stores
            }
        }
    }

    // self-reset counters for next graph replay
    __syncthreads();
    if (tid == 0) {
        red_rel_add1(bar);                          // total = 511*64 + 16
        if (cg == 0) {
            const unsigned full = 511u * 64u + 16u;
            while (ld_acq(bar) < full) { }
            atomicExch(bar, 0u);
        }
    }
}

// ---------------------------------------------------------------------------
extern "C" void kernel_launch(void* const* d_in, const int* in_sizes, int n_in,
                              void* d_out, int out_size) {
    const float* x  = (const float*)d_in[0];
    const float* Wx = (const float*)d_in[1];
    const float* Wh = (const float*)d_in[2];
    const float* bx = (const float*)d_in[3];
    const float* bh = (const float*)d_in[4];
    float* out = (float*)d_out;

    dim3 ggrid(HH / 128, (BATCH * TT) / 128);
    gemm_xw_kernel<<<ggrid, 256>>>(x, Wx, bx, bh, out);
    rnn_kernel<<<128, 256>>>(Wh, out);
}